// round 8
// baseline (speedup 1.0000x reference)
#include <cuda_runtime.h>
#include <cstdint>

// Problem constants
#define NN    50000
#define EE    800000
#define TOT_E (EE + NN)     // edges + self loops = 850000
#define IND   256
#define HID   64
#define HEADS 4
#define OUTD  256           // HEADS*HID
#define NEG_SLOPE 0.2f

// ---------------- scratch (static device globals; no allocation) ----------------
__device__ __align__(16) float  g_h[(size_t)NN * OUTD]; // projected features [N, 256]
__device__ __align__(16) float4 g_asrc[NN];             // per-node att_src logits
__device__ __align__(16) float4 g_adst[NN];             // per-node att_dst logits
__device__ __align__(16) int    g_count[NN];
__device__ __align__(16) int    g_off[NN + 1];
__device__ __align__(16) int    g_cursor[NN];
__device__ __align__(16) int    g_csrc[TOT_E];          // CSR by destination: source ids
__device__ int g_is64;                                  // edge_index dtype flag

// ---------------- K0: probe edge_index dtype ------------------------------------
// int64 indices < 50000 => every odd int32 word is 0. int32 indices => odd words
// are random node ids (overwhelmingly nonzero somewhere in 4096 samples).
__global__ void probe_kernel(const int* __restrict__ ei32) {
    int any = 0;
    for (int i = threadIdx.x * 2 + 1; i < 8192; i += 2 * blockDim.x)
        any |= ei32[i];
    any = __syncthreads_or(any);
    if (threadIdx.x == 0) g_is64 = (any == 0) ? 1 : 0;
}

__device__ __forceinline__ int load_edge(const void* eiv, int idx) {
    int v = g_is64 ? (int)((const long long*)eiv)[idx]
                   : ((const int*)eiv)[idx];
    // defensive clamp: converts any residual mismatch into a rel_err signal
    // instead of an opaque device exception.
    return min(max(v, 0), NN - 1);
}

// ---------------- K1: GEMM h = x @ W  (64x64 block tile, 4x4 per thread) --------
__global__ void gemm_kernel(const float* __restrict__ X, const float* __restrict__ W) {
    __shared__ float As[16][64];   // transposed: As[k][m]
    __shared__ float Bs[16][64];   // Bs[k][n]

    const int tid = threadIdx.x;
    const int tx = tid & 15, ty = tid >> 4;
    const int m0 = blockIdx.x * 64;
    const int n0 = blockIdx.y * 64;

    float acc[4][4] = {};

    const int arow = tid >> 2;          // 0..63
    const int acg  = (tid & 3) * 4;     // 0,4,8,12
    const int brow = tid >> 4;          // 0..15
    const int bcg  = (tid & 15) * 4;    // 0..60

    const bool avalid = (m0 + arow) < NN;
    const float* xrow = X + (size_t)(m0 + arow) * IND;

    for (int k0 = 0; k0 < IND; k0 += 16) {
        float4 av = avalid ? *(const float4*)(xrow + k0 + acg)
                           : make_float4(0.f, 0.f, 0.f, 0.f);
        As[acg + 0][arow] = av.x;
        As[acg + 1][arow] = av.y;
        As[acg + 2][arow] = av.z;
        As[acg + 3][arow] = av.w;

        float4 bv = *(const float4*)(W + (size_t)(k0 + brow) * OUTD + n0 + bcg);
        *(float4*)&Bs[brow][bcg] = bv;

        __syncthreads();
#pragma unroll
        for (int k = 0; k < 16; k++) {
            float a[4], b[4];
#pragma unroll
            for (int i = 0; i < 4; i++) a[i] = As[k][ty * 4 + i];
#pragma unroll
            for (int j = 0; j < 4; j++) b[j] = Bs[k][tx * 4 + j];
#pragma unroll
            for (int i = 0; i < 4; i++)
#pragma unroll
                for (int j = 0; j < 4; j++)
                    acc[i][j] += a[i] * b[j];
        }
        __syncthreads();
    }

#pragma unroll
    for (int i = 0; i < 4; i++) {
        const int m = m0 + ty * 4 + i;
        if (m < NN) {
            *(float4*)(g_h + (size_t)m * OUTD + n0 + tx * 4) =
                make_float4(acc[i][0], acc[i][1], acc[i][2], acc[i][3]);
        }
    }
}

// ---------------- K2: per-node attention logits ---------------------------------
__global__ void att_kernel(const float* __restrict__ att_s,
                           const float* __restrict__ att_d) {
    const int gw   = (blockIdx.x * blockDim.x + threadIdx.x) >> 5;
    const int lane = threadIdx.x & 31;
    if (gw >= NN) return;

    const float* hrow = g_h + (size_t)gw * OUTD;
    float4 h0 = *(const float4*)(hrow + lane * 8);
    float4 h1 = *(const float4*)(hrow + lane * 8 + 4);
    float4 s0 = *(const float4*)(att_s + lane * 8);
    float4 s1 = *(const float4*)(att_s + lane * 8 + 4);
    float4 d0 = *(const float4*)(att_d + lane * 8);
    float4 d1 = *(const float4*)(att_d + lane * 8 + 4);

    float ps = h0.x * s0.x + h0.y * s0.y + h0.z * s0.z + h0.w * s0.w
             + h1.x * s1.x + h1.y * s1.y + h1.z * s1.z + h1.w * s1.w;
    float pd = h0.x * d0.x + h0.y * d0.y + h0.z * d0.z + h0.w * d0.w
             + h1.x * d1.x + h1.y * d1.y + h1.z * d1.z + h1.w * d1.w;

#pragma unroll
    for (int o = 1; o < 8; o <<= 1) {
        ps += __shfl_xor_sync(0xffffffffu, ps, o);
        pd += __shfl_xor_sync(0xffffffffu, pd, o);
    }
    if ((lane & 7) == 0) {
        const int head = lane >> 3;
        ((float*)g_asrc)[(size_t)gw * 4 + head] = ps;
        ((float*)g_adst)[(size_t)gw * 4 + head] = pd;
    }
}

// ---------------- K3..K5: CSR build by destination ------------------------------
__global__ void zero_kernel() {
    int i = blockIdx.x * blockDim.x + threadIdx.x;
    if (i < NN) g_count[i] = 0;
}

__global__ void count_kernel(const void* __restrict__ eiv) {
    int e = blockIdx.x * blockDim.x + threadIdx.x;
    if (e >= TOT_E) return;
    int d = (e < EE) ? load_edge(eiv, EE + e) : (e - EE);
    atomicAdd(&g_count[d], 1);
}

__global__ void scan_kernel() {
    __shared__ int s[1024];
    const int tid = threadIdx.x;
    const int CH = (NN + 1023) / 1024;  // 49
    const int base = tid * CH;

    int mysum = 0;
    for (int i = 0; i < CH; i++) {
        int idx = base + i;
        if (idx < NN) mysum += g_count[idx];
    }
    s[tid] = mysum;
    __syncthreads();
#pragma unroll
    for (int o = 1; o < 1024; o <<= 1) {
        int t = (tid >= o) ? s[tid - o] : 0;
        __syncthreads();
        s[tid] += t;
        __syncthreads();
    }
    int excl = s[tid] - mysum;
    for (int i = 0; i < CH; i++) {
        int idx = base + i;
        if (idx < NN) {
            g_off[idx]    = excl;
            g_cursor[idx] = excl;
            excl += g_count[idx];
        }
    }
    if (tid == 1023) g_off[NN] = excl;
}

__global__ void scatter_kernel(const void* __restrict__ eiv) {
    int e = blockIdx.x * blockDim.x + threadIdx.x;
    if (e >= TOT_E) return;
    int sN, d;
    if (e < EE) { sN = load_edge(eiv, e); d = load_edge(eiv, EE + e); }
    else        { sN = d = e - EE; }
    int pos = atomicAdd(&g_cursor[d], 1);
    if (pos >= 0 && pos < TOT_E) g_csrc[pos] = sN;
}

// ---------------- K6: segment softmax + weighted aggregation --------------------
__device__ __forceinline__ float leaky(float v) {
    return v > 0.f ? v : NEG_SLOPE * v;
}

__global__ void aggregate_kernel(const float* __restrict__ bias,
                                 float* __restrict__ out) {
    const int gw   = (blockIdx.x * blockDim.x + threadIdx.x) >> 5;
    const int lane = threadIdx.x & 31;
    if (gw >= NN) return;

    const int beg = g_off[gw];
    const int end = g_off[gw + 1];
    const float4 ad = g_adst[gw];

    // pass 1: per-head max
    float m0 = -1e30f, m1 = -1e30f, m2 = -1e30f, m3 = -1e30f;
    for (int i = beg + lane; i < end; i += 32) {
        int sN = g_csrc[i];
        float4 as = g_asrc[sN];
        m0 = fmaxf(m0, leaky(as.x + ad.x));
        m1 = fmaxf(m1, leaky(as.y + ad.y));
        m2 = fmaxf(m2, leaky(as.z + ad.z));
        m3 = fmaxf(m3, leaky(as.w + ad.w));
    }
#pragma unroll
    for (int o = 16; o > 0; o >>= 1) {
        m0 = fmaxf(m0, __shfl_xor_sync(0xffffffffu, m0, o));
        m1 = fmaxf(m1, __shfl_xor_sync(0xffffffffu, m1, o));
        m2 = fmaxf(m2, __shfl_xor_sync(0xffffffffu, m2, o));
        m3 = fmaxf(m3, __shfl_xor_sync(0xffffffffu, m3, o));
    }

    // pass 2: per-head exp-sum
    float d0 = 0.f, d1 = 0.f, d2 = 0.f, d3 = 0.f;
    for (int i = beg + lane; i < end; i += 32) {
        int sN = g_csrc[i];
        float4 as = g_asrc[sN];
        d0 += __expf(leaky(as.x + ad.x) - m0);
        d1 += __expf(leaky(as.y + ad.y) - m1);
        d2 += __expf(leaky(as.z + ad.z) - m2);
        d3 += __expf(leaky(as.w + ad.w) - m3);
    }
#pragma unroll
    for (int o = 16; o > 0; o >>= 1) {
        d0 += __shfl_xor_sync(0xffffffffu, d0, o);
        d1 += __shfl_xor_sync(0xffffffffu, d1, o);
        d2 += __shfl_xor_sync(0xffffffffu, d2, o);
        d3 += __shfl_xor_sync(0xffffffffu, d3, o);
    }
    const float i0 = 1.f / d0, i1 = 1.f / d1, i2 = 1.f / d2, i3 = 1.f / d3;

    // pass 3: gather h[src] * alpha, all 32 lanes per edge
    float4 acc0 = make_float4(0.f, 0.f, 0.f, 0.f);
    float4 acc1 = make_float4(0.f, 0.f, 0.f, 0.f);
    const bool lo = (lane < 16);

    const int nume = end - beg;
    for (int base = 0; base < nume; base += 32) {
        const int cnt = min(32, nume - base);
        int sv = (base + lane < nume) ? g_csrc[beg + base + lane] : 0;
        for (int j = 0; j < cnt; j++) {
            const int sN = __shfl_sync(0xffffffffu, sv, j);
            float4 as = g_asrc[sN];
            float e0 = __expf(leaky(as.x + ad.x) - m0) * i0;
            float e1 = __expf(leaky(as.y + ad.y) - m1) * i1;
            float e2 = __expf(leaky(as.z + ad.z) - m2) * i2;
            float e3 = __expf(leaky(as.w + ad.w) - m3) * i3;
            const float w0 = lo ? e0 : e1;
            const float w1 = lo ? e2 : e3;
            const float4* hp = (const float4*)(g_h + (size_t)sN * OUTD);
            float4 v0 = hp[lane];
            float4 v1 = hp[32 + lane];
            acc0.x += w0 * v0.x; acc0.y += w0 * v0.y;
            acc0.z += w0 * v0.z; acc0.w += w0 * v0.w;
            acc1.x += w1 * v1.x; acc1.y += w1 * v1.y;
            acc1.z += w1 * v1.z; acc1.w += w1 * v1.w;
        }
    }

    float4 b0 = *(const float4*)(bias + lane * 4);
    float4 b1 = *(const float4*)(bias + 128 + lane * 4);
    acc0.x = fmaxf(acc0.x + b0.x, 0.f); acc0.y = fmaxf(acc0.y + b0.y, 0.f);
    acc0.z = fmaxf(acc0.z + b0.z, 0.f); acc0.w = fmaxf(acc0.w + b0.w, 0.f);
    acc1.x = fmaxf(acc1.x + b1.x, 0.f); acc1.y = fmaxf(acc1.y + b1.y, 0.f);
    acc1.z = fmaxf(acc1.z + b1.z, 0.f); acc1.w = fmaxf(acc1.w + b1.w, 0.f);

    float4* op = (float4*)(out + (size_t)gw * OUTD);
    op[lane]      = acc0;
    op[32 + lane] = acc1;
}

// ---------------- launch --------------------------------------------------------
extern "C" void kernel_launch(void* const* d_in, const int* in_sizes, int n_in,
                              void* d_out, int out_size) {
    // Size-based dispatch: robust against metadata ordering surprises.
    // x: 12,800,000 | W: 65,536 | edge_index: ~1.6M | att_src/att_dst/bias: 256 each
    const float* x = nullptr; const void* ei = nullptr; const float* W = nullptr;
    const float* att_src = nullptr; const float* att_dst = nullptr;
    const float* bias = nullptr;
    for (int i = 0; i < n_in; i++) {
        const int sz = in_sizes[i];
        if (sz == 12800000)      { x = (const float*)d_in[i]; }
        else if (sz == 65536)    { W = (const float*)d_in[i]; }
        else if (sz >= 1000000)  { ei = d_in[i]; }
        else if (sz == 256) {
            if      (!att_src) att_src = (const float*)d_in[i];
            else if (!att_dst) att_dst = (const float*)d_in[i];
            else if (!bias)    bias    = (const float*)d_in[i];
        }
    }
    float* out = (float*)d_out;
    (void)out_size;
    if (!x || !ei || !W || !att_src || !att_dst || !bias) return;

    // 0. detect edge_index storage dtype (int32 vs int64)
    probe_kernel<<<1, 256>>>((const int*)ei);
    // 1. projection GEMM (writes g_h)
    gemm_kernel<<<dim3((NN + 63) / 64, OUTD / 64), 256>>>(x, W);
    // 2. per-node attention logits
    att_kernel<<<(NN + 7) / 8, 256>>>(att_src, att_dst);
    // 3. CSR by destination
    zero_kernel<<<(NN + 255) / 256, 256>>>();
    count_kernel<<<(TOT_E + 255) / 256, 256>>>(ei);
    scan_kernel<<<1, 1024>>>();
    scatter_kernel<<<(TOT_E + 255) / 256, 256>>>(ei);
    // 4. segment softmax + aggregation + bias + relu
    aggregate_kernel<<<(NN + 7) / 8, 256>>>(bias, out);
}

// round 9
// speedup vs baseline: 1.6125x; 1.6125x over previous
#include <cuda_runtime.h>
#include <cstdint>

// Problem constants
#define NN    50000
#define EE    800000
#define TOT_E (EE + NN)     // edges + self loops = 850000
#define IND   256
#define HID   64
#define HEADS 4
#define OUTD  256           // HEADS*HID
#define NEG_SLOPE 0.2f

// ---------------- scratch (static device globals; no allocation) ----------------
__device__ __align__(16) float  g_h[(size_t)NN * OUTD]; // projected features [N, 256]
__device__ __align__(16) float4 g_asrc[NN];             // per-node att_src logits
__device__ __align__(16) float4 g_adst[NN];             // per-node att_dst logits
__device__ __align__(16) int    g_count[NN];
__device__ __align__(16) int    g_off[NN + 1];
__device__ __align__(16) int    g_cursor[NN];
__device__ __align__(16) int    g_csrc[TOT_E];          // CSR by destination: source ids
__device__ int g_is64;                                  // edge_index dtype flag

// ---------------- K0: probe edge_index dtype ------------------------------------
__global__ void probe_kernel(const int* __restrict__ ei32) {
    int any = 0;
    for (int i = threadIdx.x * 2 + 1; i < 8192; i += 2 * blockDim.x)
        any |= ei32[i];
    any = __syncthreads_or(any);
    if (threadIdx.x == 0) g_is64 = (any == 0) ? 1 : 0;
}

__device__ __forceinline__ int load_edge(const void* eiv, int idx) {
    int v = g_is64 ? (int)((const long long*)eiv)[idx]
                   : ((const int*)eiv)[idx];
    return min(max(v, 0), NN - 1);
}

// ---------------- K1: GEMM h = x @ W  (64x64 block tile, 4x4 per thread) --------
__global__ void gemm_kernel(const float* __restrict__ X, const float* __restrict__ W) {
    __shared__ float As[16][64];   // transposed: As[k][m]
    __shared__ float Bs[16][64];   // Bs[k][n]

    const int tid = threadIdx.x;
    const int tx = tid & 15, ty = tid >> 4;
    const int m0 = blockIdx.x * 64;
    const int n0 = blockIdx.y * 64;

    float acc[4][4] = {};

    const int arow = tid >> 2;          // 0..63
    const int acg  = (tid & 3) * 4;     // 0,4,8,12
    const int brow = tid >> 4;          // 0..15
    const int bcg  = (tid & 15) * 4;    // 0..60

    const bool avalid = (m0 + arow) < NN;
    const float* xrow = X + (size_t)(m0 + arow) * IND;

    for (int k0 = 0; k0 < IND; k0 += 16) {
        float4 av = avalid ? *(const float4*)(xrow + k0 + acg)
                           : make_float4(0.f, 0.f, 0.f, 0.f);
        As[acg + 0][arow] = av.x;
        As[acg + 1][arow] = av.y;
        As[acg + 2][arow] = av.z;
        As[acg + 3][arow] = av.w;

        float4 bv = *(const float4*)(W + (size_t)(k0 + brow) * OUTD + n0 + bcg);
        *(float4*)&Bs[brow][bcg] = bv;

        __syncthreads();
#pragma unroll
        for (int k = 0; k < 16; k++) {
            float a[4], b[4];
#pragma unroll
            for (int i = 0; i < 4; i++) a[i] = As[k][ty * 4 + i];
#pragma unroll
            for (int j = 0; j < 4; j++) b[j] = Bs[k][tx * 4 + j];
#pragma unroll
            for (int i = 0; i < 4; i++)
#pragma unroll
                for (int j = 0; j < 4; j++)
                    acc[i][j] += a[i] * b[j];
        }
        __syncthreads();
    }

#pragma unroll
    for (int i = 0; i < 4; i++) {
        const int m = m0 + ty * 4 + i;
        if (m < NN) {
            *(float4*)(g_h + (size_t)m * OUTD + n0 + tx * 4) =
                make_float4(acc[i][0], acc[i][1], acc[i][2], acc[i][3]);
        }
    }
}

// ---------------- K2: per-node attention logits ---------------------------------
__global__ void att_kernel(const float* __restrict__ att_s,
                           const float* __restrict__ att_d) {
    const int gw   = (blockIdx.x * blockDim.x + threadIdx.x) >> 5;
    const int lane = threadIdx.x & 31;
    if (gw >= NN) return;

    const float* hrow = g_h + (size_t)gw * OUTD;
    float4 h0 = *(const float4*)(hrow + lane * 8);
    float4 h1 = *(const float4*)(hrow + lane * 8 + 4);
    float4 s0 = *(const float4*)(att_s + lane * 8);
    float4 s1 = *(const float4*)(att_s + lane * 8 + 4);
    float4 d0 = *(const float4*)(att_d + lane * 8);
    float4 d1 = *(const float4*)(att_d + lane * 8 + 4);

    float ps = h0.x * s0.x + h0.y * s0.y + h0.z * s0.z + h0.w * s0.w
             + h1.x * s1.x + h1.y * s1.y + h1.z * s1.z + h1.w * s1.w;
    float pd = h0.x * d0.x + h0.y * d0.y + h0.z * d0.z + h0.w * d0.w
             + h1.x * d1.x + h1.y * d1.y + h1.z * d1.z + h1.w * d1.w;

#pragma unroll
    for (int o = 1; o < 8; o <<= 1) {
        ps += __shfl_xor_sync(0xffffffffu, ps, o);
        pd += __shfl_xor_sync(0xffffffffu, pd, o);
    }
    if ((lane & 7) == 0) {
        const int head = lane >> 3;
        ((float*)g_asrc)[(size_t)gw * 4 + head] = ps;
        ((float*)g_adst)[(size_t)gw * 4 + head] = pd;
    }
}

// ---------------- K3..K5: CSR build by destination ------------------------------
__global__ void zero_kernel() {
    int i = blockIdx.x * blockDim.x + threadIdx.x;
    if (i < NN) g_count[i] = 0;
}

__global__ void count_kernel(const void* __restrict__ eiv) {
    int e = blockIdx.x * blockDim.x + threadIdx.x;
    if (e >= TOT_E) return;
    int d = (e < EE) ? load_edge(eiv, EE + e) : (e - EE);
    atomicAdd(&g_count[d], 1);
}

__global__ void scan_kernel() {
    __shared__ int s[1024];
    const int tid = threadIdx.x;
    const int CH = (NN + 1023) / 1024;  // 49
    const int base = tid * CH;

    int mysum = 0;
    for (int i = 0; i < CH; i++) {
        int idx = base + i;
        if (idx < NN) mysum += g_count[idx];
    }
    s[tid] = mysum;
    __syncthreads();
#pragma unroll
    for (int o = 1; o < 1024; o <<= 1) {
        int t = (tid >= o) ? s[tid - o] : 0;
        __syncthreads();
        s[tid] += t;
        __syncthreads();
    }
    int excl = s[tid] - mysum;
    for (int i = 0; i < CH; i++) {
        int idx = base + i;
        if (idx < NN) {
            g_off[idx]    = excl;
            g_cursor[idx] = excl;
            excl += g_count[idx];
        }
    }
    if (tid == 1023) g_off[NN] = excl;
}

__global__ void scatter_kernel(const void* __restrict__ eiv) {
    int e = blockIdx.x * blockDim.x + threadIdx.x;
    if (e >= TOT_E) return;
    int sN, d;
    if (e < EE) { sN = load_edge(eiv, e); d = load_edge(eiv, EE + e); }
    else        { sN = d = e - EE; }
    int pos = atomicAdd(&g_cursor[d], 1);
    if (pos >= 0 && pos < TOT_E) g_csrc[pos] = sN;
}

// ---------------- K6: segment softmax + weighted aggregation --------------------
__device__ __forceinline__ float leaky(float v) {
    return v > 0.f ? v : NEG_SLOPE * v;
}

__global__ void aggregate_kernel(const float* __restrict__ bias,
                                 float* __restrict__ out) {
    const int gw   = (blockIdx.x * blockDim.x + threadIdx.x) >> 5;
    const int lane = threadIdx.x & 31;
    if (gw >= NN) return;

    const int beg = g_off[gw];
    const int end = g_off[gw + 1];
    const float4 ad = g_adst[gw];

    // pass 1: per-head max
    float m0 = -1e30f, m1 = -1e30f, m2 = -1e30f, m3 = -1e30f;
    for (int i = beg + lane; i < end; i += 32) {
        int sN = g_csrc[i];
        float4 as = g_asrc[sN];
        m0 = fmaxf(m0, leaky(as.x + ad.x));
        m1 = fmaxf(m1, leaky(as.y + ad.y));
        m2 = fmaxf(m2, leaky(as.z + ad.z));
        m3 = fmaxf(m3, leaky(as.w + ad.w));
    }
#pragma unroll
    for (int o = 16; o > 0; o >>= 1) {
        m0 = fmaxf(m0, __shfl_xor_sync(0xffffffffu, m0, o));
        m1 = fmaxf(m1, __shfl_xor_sync(0xffffffffu, m1, o));
        m2 = fmaxf(m2, __shfl_xor_sync(0xffffffffu, m2, o));
        m3 = fmaxf(m3, __shfl_xor_sync(0xffffffffu, m3, o));
    }

    // pass 2: per-head exp-sum
    float d0 = 0.f, d1 = 0.f, d2 = 0.f, d3 = 0.f;
    for (int i = beg + lane; i < end; i += 32) {
        int sN = g_csrc[i];
        float4 as = g_asrc[sN];
        d0 += __expf(leaky(as.x + ad.x) - m0);
        d1 += __expf(leaky(as.y + ad.y) - m1);
        d2 += __expf(leaky(as.z + ad.z) - m2);
        d3 += __expf(leaky(as.w + ad.w) - m3);
    }
#pragma unroll
    for (int o = 16; o > 0; o >>= 1) {
        d0 += __shfl_xor_sync(0xffffffffu, d0, o);
        d1 += __shfl_xor_sync(0xffffffffu, d1, o);
        d2 += __shfl_xor_sync(0xffffffffu, d2, o);
        d3 += __shfl_xor_sync(0xffffffffu, d3, o);
    }
    const float i0 = 1.f / d0, i1 = 1.f / d1, i2 = 1.f / d2, i3 = 1.f / d3;

    // pass 3: gather h[src] * alpha.
    // Each lane computes the 4 softmax weights for ITS OWN edge once (3.4M expf
    // total vs 109M before), then the inner loop broadcasts them via SHFL.
    // acc0: features lane*4      (head = lane/16 in {0,1})
    // acc1: features 128+lane*4  (head = 2+lane/16 in {2,3})
    float4 acc0 = make_float4(0.f, 0.f, 0.f, 0.f);
    float4 acc1 = make_float4(0.f, 0.f, 0.f, 0.f);
    const bool lo = (lane < 16);

    const int nume = end - beg;
    for (int base = 0; base < nume; base += 32) {
        const int cnt = min(32, nume - base);
        const bool valid = (base + lane < nume);
        int   sv = valid ? g_csrc[beg + base + lane] : 0;
        float a0 = 0.f, a1 = 0.f, a2 = 0.f, a3 = 0.f;
        if (valid) {
            float4 as = g_asrc[sv];
            a0 = __expf(leaky(as.x + ad.x) - m0) * i0;
            a1 = __expf(leaky(as.y + ad.y) - m1) * i1;
            a2 = __expf(leaky(as.z + ad.z) - m2) * i2;
            a3 = __expf(leaky(as.w + ad.w) - m3) * i3;
        }
        for (int j = 0; j < cnt; j++) {
            const int   sN = __shfl_sync(0xffffffffu, sv, j);
            const float s0 = __shfl_sync(0xffffffffu, a0, j);
            const float s1 = __shfl_sync(0xffffffffu, a1, j);
            const float s2 = __shfl_sync(0xffffffffu, a2, j);
            const float s3 = __shfl_sync(0xffffffffu, a3, j);
            const float w0 = lo ? s0 : s1;
            const float w1 = lo ? s2 : s3;
            const float4* hp = (const float4*)(g_h + (size_t)sN * OUTD);
            float4 v0 = hp[lane];
            float4 v1 = hp[32 + lane];
            acc0.x += w0 * v0.x; acc0.y += w0 * v0.y;
            acc0.z += w0 * v0.z; acc0.w += w0 * v0.w;
            acc1.x += w1 * v1.x; acc1.y += w1 * v1.y;
            acc1.z += w1 * v1.z; acc1.w += w1 * v1.w;
        }
    }

    float4 b0 = *(const float4*)(bias + lane * 4);
    float4 b1 = *(const float4*)(bias + 128 + lane * 4);
    acc0.x = fmaxf(acc0.x + b0.x, 0.f); acc0.y = fmaxf(acc0.y + b0.y, 0.f);
    acc0.z = fmaxf(acc0.z + b0.z, 0.f); acc0.w = fmaxf(acc0.w + b0.w, 0.f);
    acc1.x = fmaxf(acc1.x + b1.x, 0.f); acc1.y = fmaxf(acc1.y + b1.y, 0.f);
    acc1.z = fmaxf(acc1.z + b1.z, 0.f); acc1.w = fmaxf(acc1.w + b1.w, 0.f);

    float4* op = (float4*)(out + (size_t)gw * OUTD);
    op[lane]      = acc0;
    op[32 + lane] = acc1;
}

// ---------------- launch --------------------------------------------------------
extern "C" void kernel_launch(void* const* d_in, const int* in_sizes, int n_in,
                              void* d_out, int out_size) {
    const float* x = nullptr; const void* ei = nullptr; const float* W = nullptr;
    const float* att_src = nullptr; const float* att_dst = nullptr;
    const float* bias = nullptr;
    for (int i = 0; i < n_in; i++) {
        const int sz = in_sizes[i];
        if (sz == 12800000)      { x = (const float*)d_in[i]; }
        else if (sz == 65536)    { W = (const float*)d_in[i]; }
        else if (sz >= 1000000)  { ei = d_in[i]; }
        else if (sz == 256) {
            if      (!att_src) att_src = (const float*)d_in[i];
            else if (!att_dst) att_dst = (const float*)d_in[i];
            else if (!bias)    bias    = (const float*)d_in[i];
        }
    }
    float* out = (float*)d_out;
    (void)out_size;
    if (!x || !ei || !W || !att_src || !att_dst || !bias) return;

    probe_kernel<<<1, 256>>>((const int*)ei);
    gemm_kernel<<<dim3((NN + 63) / 64, OUTD / 64), 256>>>(x, W);
    att_kernel<<<(NN + 7) / 8, 256>>>(att_src, att_dst);
    zero_kernel<<<(NN + 255) / 256, 256>>>();
    count_kernel<<<(TOT_E + 255) / 256, 256>>>(ei);
    scan_kernel<<<1, 1024>>>();
    scatter_kernel<<<(TOT_E + 255) / 256, 256>>>(ei);
    aggregate_kernel<<<(NN + 7) / 8, 256>>>(bias, out);
}

// round 11
// speedup vs baseline: 1.8927x; 1.1738x over previous
#include <cuda_runtime.h>
#include <cuda_bf16.h>
#include <mma.h>
#include <cstdint>

using namespace nvcuda;

// Problem constants
#define NN    50000
#define EE    800000
#define TOT_E (EE + NN)
#define IND   256
#define HID   64
#define HEADS 4
#define OUTD  256
#define NEG_SLOPE 0.2f

// GEMM tiling (wmma m16n16k16 bf16)
#define BM 128
#define BN 64
#define BK 64
#define LDS_AB 72                 // smem leading dim (elems), pad 8 vs 64
#define NN_PAD 50048              // 391 * 128 (grid-aligned padding)

// ---------------- scratch (static device globals) -------------------------------
__device__ __align__(16) float  g_h[(size_t)NN_PAD * OUTD];
__device__ __align__(16) __nv_bfloat16 g_xhi[(size_t)NN_PAD * IND];
__device__ __align__(16) __nv_bfloat16 g_xlo[(size_t)NN_PAD * IND];
__device__ __align__(16) __nv_bfloat16 g_whi[IND * OUTD];   // W [k][n], bf16 hi
__device__ __align__(16) __nv_bfloat16 g_wlo[IND * OUTD];   // W [k][n], bf16 lo
__device__ __align__(16) float4 g_asrc[NN];
__device__ __align__(16) float4 g_adst[NN];
__device__ __align__(16) int    g_count[NN];
__device__ __align__(16) int    g_off[NN + 1];
__device__ __align__(16) int    g_cursor[NN];
__device__ __align__(16) int    g_csrc[TOT_E];
__device__ int g_is64;

// ---------------- K0: probe edge_index dtype ------------------------------------
__global__ void probe_kernel(const int* __restrict__ ei32) {
    int any = 0;
    for (int i = threadIdx.x * 2 + 1; i < 8192; i += 2 * blockDim.x)
        any |= ei32[i];
    any = __syncthreads_or(any);
    if (threadIdx.x == 0) g_is64 = (any == 0) ? 1 : 0;
}
__device__ __forceinline__ int load_edge(const void* eiv, int idx) {
    int v = g_is64 ? (int)((const long long*)eiv)[idx] : ((const int*)eiv)[idx];
    return min(max(v, 0), NN - 1);
}

// ---------------- split-bf16 conversions ----------------------------------------
__global__ void convx_kernel(const float* __restrict__ x) {
    size_t i = (size_t)blockIdx.x * blockDim.x + threadIdx.x;   // one float4
    const size_t tot = (size_t)NN_PAD * IND / 4;
    if (i >= tot) return;
    float4 v = (i < (size_t)NN * IND / 4) ? ((const float4*)x)[i]
                                          : make_float4(0.f, 0.f, 0.f, 0.f);
    __nv_bfloat16 h0 = __float2bfloat16(v.x), h1 = __float2bfloat16(v.y);
    __nv_bfloat16 h2 = __float2bfloat16(v.z), h3 = __float2bfloat16(v.w);
    __nv_bfloat16 l0 = __float2bfloat16(v.x - __bfloat162float(h0));
    __nv_bfloat16 l1 = __float2bfloat16(v.y - __bfloat162float(h1));
    __nv_bfloat16 l2 = __float2bfloat16(v.z - __bfloat162float(h2));
    __nv_bfloat16 l3 = __float2bfloat16(v.w - __bfloat162float(h3));
    __nv_bfloat162* ph = (__nv_bfloat162*)g_xhi;
    __nv_bfloat162* pl = (__nv_bfloat162*)g_xlo;
    ph[i * 2]     = __nv_bfloat162(h0, h1);
    ph[i * 2 + 1] = __nv_bfloat162(h2, h3);
    pl[i * 2]     = __nv_bfloat162(l0, l1);
    pl[i * 2 + 1] = __nv_bfloat162(l2, l3);
}

__global__ void convw_kernel(const float* __restrict__ W) {
    int i = blockIdx.x * blockDim.x + threadIdx.x;   // k*256+n (layout preserved)
    if (i >= IND * OUTD) return;
    float v = W[i];
    __nv_bfloat16 h = __float2bfloat16(v);
    g_whi[i] = h;
    g_wlo[i] = __float2bfloat16(v - __bfloat162float(h));
}

// ---------------- K1: HMMA GEMM h = x @ W (split-bf16, 3 products) --------------
// smem layout (dynamic): As_hi | As_lo | Bs_hi | Bs_lo
#define SM_AHI 0
#define SM_ALO (BM * LDS_AB * 2)                    // 18432
#define SM_BHI (2 * BM * LDS_AB * 2)                // 36864
#define SM_BLO (2 * BM * LDS_AB * 2 + BK * LDS_AB * 2)  // 46080
#define SM_GEMM_TOTAL (2 * BM * LDS_AB * 2 + 2 * BK * LDS_AB * 2)  // 55296

__global__ void __launch_bounds__(256, 1) gemm_wmma_kernel() {
    extern __shared__ char smem[];
    __nv_bfloat16* As_hi = (__nv_bfloat16*)(smem + SM_AHI);
    __nv_bfloat16* As_lo = (__nv_bfloat16*)(smem + SM_ALO);
    __nv_bfloat16* Bs_hi = (__nv_bfloat16*)(smem + SM_BHI);
    __nv_bfloat16* Bs_lo = (__nv_bfloat16*)(smem + SM_BLO);

    const int tid = threadIdx.x;
    const int wid = tid >> 5;
    const int warp_m = wid >> 1;          // 0..3
    const int warp_n = wid & 1;           // 0..1
    const int m0 = blockIdx.x * BM;
    const int n0 = blockIdx.y * BN;

    wmma::fragment<wmma::accumulator, 16, 16, 16, float> acc[2][2];
#pragma unroll
    for (int mi = 0; mi < 2; mi++)
#pragma unroll
        for (int ni = 0; ni < 2; ni++)
            wmma::fill_fragment(acc[mi][ni], 0.f);

    for (int kt = 0; kt < IND; kt += BK) {
        // A tile: BM x BK bf16 hi+lo. 1024 uint4 per matrix, 4 per thread.
#pragma unroll
        for (int it = 0; it < 4; it++) {
            const int idx = tid + it * 256;
            const int row = idx >> 3, c8 = (idx & 7) * 8;
            const size_t e = (size_t)(m0 + row) * IND + kt + c8;
            *(uint4*)(As_hi + row * LDS_AB + c8) = *(const uint4*)(g_xhi + e);
            *(uint4*)(As_lo + row * LDS_AB + c8) = *(const uint4*)(g_xlo + e);
        }
        // B tile: BK x BN bf16 hi+lo. 512 uint4 per matrix, 2 per thread.
#pragma unroll
        for (int it = 0; it < 2; it++) {
            const int idx = tid + it * 256;
            const int row = idx >> 3, c8 = (idx & 7) * 8;
            const size_t e = (size_t)(kt + row) * OUTD + n0 + c8;
            *(uint4*)(Bs_hi + row * LDS_AB + c8) = *(const uint4*)(g_whi + e);
            *(uint4*)(Bs_lo + row * LDS_AB + c8) = *(const uint4*)(g_wlo + e);
        }
        __syncthreads();

#pragma unroll
        for (int ks = 0; ks < BK; ks += 16) {
            wmma::fragment<wmma::matrix_a, 16, 16, 16, __nv_bfloat16, wmma::row_major> a_hi[2], a_lo[2];
            wmma::fragment<wmma::matrix_b, 16, 16, 16, __nv_bfloat16, wmma::row_major> b_hi[2], b_lo[2];
#pragma unroll
            for (int mi = 0; mi < 2; mi++) {
                const int r = warp_m * 32 + mi * 16;
                wmma::load_matrix_sync(a_hi[mi], As_hi + r * LDS_AB + ks, LDS_AB);
                wmma::load_matrix_sync(a_lo[mi], As_lo + r * LDS_AB + ks, LDS_AB);
            }
#pragma unroll
            for (int ni = 0; ni < 2; ni++) {
                const int c = warp_n * 32 + ni * 16;
                wmma::load_matrix_sync(b_hi[ni], Bs_hi + ks * LDS_AB + c, LDS_AB);
                wmma::load_matrix_sync(b_lo[ni], Bs_lo + ks * LDS_AB + c, LDS_AB);
            }
#pragma unroll
            for (int mi = 0; mi < 2; mi++)
#pragma unroll
                for (int ni = 0; ni < 2; ni++) {
                    wmma::mma_sync(acc[mi][ni], a_hi[mi], b_hi[ni], acc[mi][ni]);
                    wmma::mma_sync(acc[mi][ni], a_hi[mi], b_lo[ni], acc[mi][ni]);
                    wmma::mma_sync(acc[mi][ni], a_lo[mi], b_hi[ni], acc[mi][ni]);
                }
        }
        __syncthreads();
    }

    // epilogue: unguarded stores into padded g_h
#pragma unroll
    for (int mi = 0; mi < 2; mi++)
#pragma unroll
        for (int ni = 0; ni < 2; ni++) {
            const int r = m0 + warp_m * 32 + mi * 16;
            const int c = n0 + warp_n * 32 + ni * 16;
            wmma::store_matrix_sync(g_h + (size_t)r * OUTD + c, acc[mi][ni],
                                    OUTD, wmma::mem_row_major);
        }
}

// ---------------- K2: per-node attention logits ---------------------------------
__global__ void att_kernel(const float* __restrict__ att_s,
                           const float* __restrict__ att_d) {
    const int gw   = (blockIdx.x * blockDim.x + threadIdx.x) >> 5;
    const int lane = threadIdx.x & 31;
    if (gw >= NN) return;

    const float* hrow = g_h + (size_t)gw * OUTD;
    float4 h0 = *(const float4*)(hrow + lane * 8);
    float4 h1 = *(const float4*)(hrow + lane * 8 + 4);
    float4 s0 = *(const float4*)(att_s + lane * 8);
    float4 s1 = *(const float4*)(att_s + lane * 8 + 4);
    float4 d0 = *(const float4*)(att_d + lane * 8);
    float4 d1 = *(const float4*)(att_d + lane * 8 + 4);

    float ps = h0.x * s0.x + h0.y * s0.y + h0.z * s0.z + h0.w * s0.w
             + h1.x * s1.x + h1.y * s1.y + h1.z * s1.z + h1.w * s1.w;
    float pd = h0.x * d0.x + h0.y * d0.y + h0.z * d0.z + h0.w * d0.w
             + h1.x * d1.x + h1.y * d1.y + h1.z * d1.z + h1.w * d1.w;

#pragma unroll
    for (int o = 1; o < 8; o <<= 1) {
        ps += __shfl_xor_sync(0xffffffffu, ps, o);
        pd += __shfl_xor_sync(0xffffffffu, pd, o);
    }
    if ((lane & 7) == 0) {
        const int head = lane >> 3;
        ((float*)g_asrc)[(size_t)gw * 4 + head] = ps;
        ((float*)g_adst)[(size_t)gw * 4 + head] = pd;
    }
}

// ---------------- CSR build by destination --------------------------------------
__global__ void zero_kernel() {
    int i = blockIdx.x * blockDim.x + threadIdx.x;
    if (i < NN) g_count[i] = 0;
}
__global__ void count_kernel(const void* __restrict__ eiv) {
    int e = blockIdx.x * blockDim.x + threadIdx.x;
    if (e >= TOT_E) return;
    int d = (e < EE) ? load_edge(eiv, EE + e) : (e - EE);
    atomicAdd(&g_count[d], 1);
}
__global__ void scan_kernel() {
    __shared__ int s[1024];
    const int tid = threadIdx.x;
    const int CH = (NN + 1023) / 1024;
    const int base = tid * CH;
    int mysum = 0;
    for (int i = 0; i < CH; i++) {
        int idx = base + i;
        if (idx < NN) mysum += g_count[idx];
    }
    s[tid] = mysum;
    __syncthreads();
#pragma unroll
    for (int o = 1; o < 1024; o <<= 1) {
        int t = (tid >= o) ? s[tid - o] : 0;
        __syncthreads();
        s[tid] += t;
        __syncthreads();
    }
    int excl = s[tid] - mysum;
    for (int i = 0; i < CH; i++) {
        int idx = base + i;
        if (idx < NN) {
            g_off[idx]    = excl;
            g_cursor[idx] = excl;
            excl += g_count[idx];
        }
    }
    if (tid == 1023) g_off[NN] = excl;
}
__global__ void scatter_kernel(const void* __restrict__ eiv) {
    int e = blockIdx.x * blockDim.x + threadIdx.x;
    if (e >= TOT_E) return;
    int sN, d;
    if (e < EE) { sN = load_edge(eiv, e); d = load_edge(eiv, EE + e); }
    else        { sN = d = e - EE; }
    int pos = atomicAdd(&g_cursor[d], 1);
    if (pos >= 0 && pos < TOT_E) g_csrc[pos] = sN;
}

// ---------------- K6: segment softmax + weighted aggregation --------------------
__device__ __forceinline__ float leaky(float v) {
    return v > 0.f ? v : NEG_SLOPE * v;
}

__global__ void aggregate_kernel(const float* __restrict__ bias,
                                 float* __restrict__ out) {
    const int gw   = (blockIdx.x * blockDim.x + threadIdx.x) >> 5;
    const int lane = threadIdx.x & 31;
    if (gw >= NN) return;

    const int beg = g_off[gw];
    const int end = g_off[gw + 1];
    const float4 ad = g_adst[gw];

    float m0 = -1e30f, m1 = -1e30f, m2 = -1e30f, m3 = -1e30f;
    for (int i = beg + lane; i < end; i += 32) {
        int sN = g_csrc[i];
        float4 as = g_asrc[sN];
        m0 = fmaxf(m0, leaky(as.x + ad.x));
        m1 = fmaxf(m1, leaky(as.y + ad.y));
        m2 = fmaxf(m2, leaky(as.z + ad.z));
        m3 = fmaxf(m3, leaky(as.w + ad.w));
    }
#pragma unroll
    for (int o = 16; o > 0; o >>= 1) {
        m0 = fmaxf(m0, __shfl_xor_sync(0xffffffffu, m0, o));
        m1 = fmaxf(m1, __shfl_xor_sync(0xffffffffu, m1, o));
        m2 = fmaxf(m2, __shfl_xor_sync(0xffffffffu, m2, o));
        m3 = fmaxf(m3, __shfl_xor_sync(0xffffffffu, m3, o));
    }

    float d0 = 0.f, d1 = 0.f, d2 = 0.f, d3 = 0.f;
    for (int i = beg + lane; i < end; i += 32) {
        int sN = g_csrc[i];
        float4 as = g_asrc[sN];
        d0 += __expf(leaky(as.x + ad.x) - m0);
        d1 += __expf(leaky(as.y + ad.y) - m1);
        d2 += __expf(leaky(as.z + ad.z) - m2);
        d3 += __expf(leaky(as.w + ad.w) - m3);
    }
#pragma unroll
    for (int o = 16; o > 0; o >>= 1) {
        d0 += __shfl_xor_sync(0xffffffffu, d0, o);
        d1 += __shfl_xor_sync(0xffffffffu, d1, o);
        d2 += __shfl_xor_sync(0xffffffffu, d2, o);
        d3 += __shfl_xor_sync(0xffffffffu, d3, o);
    }
    const float i0 = 1.f / d0, i1 = 1.f / d1, i2 = 1.f / d2, i3 = 1.f / d3;

    float4 acc0 = make_float4(0.f, 0.f, 0.f, 0.f);
    float4 acc1 = make_float4(0.f, 0.f, 0.f, 0.f);
    const bool lo = (lane < 16);

    const int nume = end - beg;
    for (int base = 0; base < nume; base += 32) {
        const int cnt = min(32, nume - base);
        const bool valid = (base + lane < nume);
        int   sv = valid ? g_csrc[beg + base + lane] : 0;
        float a0 = 0.f, a1 = 0.f, a2 = 0.f, a3 = 0.f;
        if (valid) {
            float4 as = g_asrc[sv];
            a0 = __expf(leaky(as.x + ad.x) - m0) * i0;
            a1 = __expf(leaky(as.y + ad.y) - m1) * i1;
            a2 = __expf(leaky(as.z + ad.z) - m2) * i2;
            a3 = __expf(leaky(as.w + ad.w) - m3) * i3;
        }
        for (int j = 0; j < cnt; j++) {
            const int   sN = __shfl_sync(0xffffffffu, sv, j);
            const float s0 = __shfl_sync(0xffffffffu, a0, j);
            const float s1 = __shfl_sync(0xffffffffu, a1, j);
            const float s2 = __shfl_sync(0xffffffffu, a2, j);
            const float s3 = __shfl_sync(0xffffffffu, a3, j);
            const float w0 = lo ? s0 : s1;
            const float w1 = lo ? s2 : s3;
            const float4* hp = (const float4*)(g_h + (size_t)sN * OUTD);
            float4 v0 = hp[lane];
            float4 v1 = hp[32 + lane];
            acc0.x += w0 * v0.x; acc0.y += w0 * v0.y;
            acc0.z += w0 * v0.z; acc0.w += w0 * v0.w;
            acc1.x += w1 * v1.x; acc1.y += w1 * v1.y;
            acc1.z += w1 * v1.z; acc1.w += w1 * v1.w;
        }
    }

    float4 b0 = *(const float4*)(bias + lane * 4);
    float4 b1 = *(const float4*)(bias + 128 + lane * 4);
    acc0.x = fmaxf(acc0.x + b0.x, 0.f); acc0.y = fmaxf(acc0.y + b0.y, 0.f);
    acc0.z = fmaxf(acc0.z + b0.z, 0.f); acc0.w = fmaxf(acc0.w + b0.w, 0.f);
    acc1.x = fmaxf(acc1.x + b1.x, 0.f); acc1.y = fmaxf(acc1.y + b1.y, 0.f);
    acc1.z = fmaxf(acc1.z + b1.z, 0.f); acc1.w = fmaxf(acc1.w + b1.w, 0.f);

    float4* op = (float4*)(out + (size_t)gw * OUTD);
    op[lane]      = acc0;
    op[32 + lane] = acc1;
}

// ---------------- launch --------------------------------------------------------
extern "C" void kernel_launch(void* const* d_in, const int* in_sizes, int n_in,
                              void* d_out, int out_size) {
    const float* x = nullptr; const void* ei = nullptr; const float* W = nullptr;
    const float* att_src = nullptr; const float* att_dst = nullptr;
    const float* bias = nullptr;
    for (int i = 0; i < n_in; i++) {
        const int sz = in_sizes[i];
        if (sz == 12800000)      { x = (const float*)d_in[i]; }
        else if (sz == 65536)    { W = (const float*)d_in[i]; }
        else if (sz >= 1000000)  { ei = d_in[i]; }
        else if (sz == 256) {
            if      (!att_src) att_src = (const float*)d_in[i];
            else if (!att_dst) att_dst = (const float*)d_in[i];
            else if (!bias)    bias    = (const float*)d_in[i];
        }
    }
    float* out = (float*)d_out;
    (void)out_size;
    if (!x || !ei || !W || !att_src || !att_dst || !bias) return;

    static bool attr_set = false;
    if (!attr_set) {
        cudaFuncSetAttribute(gemm_wmma_kernel,
                             cudaFuncAttributeMaxDynamicSharedMemorySize,
                             SM_GEMM_TOTAL);
        attr_set = true;
    }

    probe_kernel<<<1, 256>>>((const int*)ei);
    convw_kernel<<<(IND * OUTD + 255) / 256, 256>>>(W);
    convx_kernel<<<(int)(((size_t)NN_PAD * IND / 4 + 255) / 256), 256>>>(x);
    gemm_wmma_kernel<<<dim3(NN_PAD / BM, OUTD / BN), 256, SM_GEMM_TOTAL>>>();
    att_kernel<<<(NN + 7) / 8, 256>>>(att_src, att_dst);
    zero_kernel<<<(NN + 255) / 256, 256>>>();
    count_kernel<<<(TOT_E + 255) / 256, 256>>>(ei);
    scan_kernel<<<1, 1024>>>();
    scatter_kernel<<<(TOT_E + 255) / 256, 256>>>(ei);
    aggregate_kernel<<<(NN + 7) / 8, 256>>>(bias, out);
}

// round 14
// speedup vs baseline: 2.5660x; 1.3558x over previous
#include <cuda_runtime.h>
#include <cuda_bf16.h>
#include <mma.h>
#include <cstdint>

using namespace nvcuda;

// Problem constants
#define NN    50000
#define EE    800000
#define TOT_E (EE + NN)
#define IND   256
#define HID   64
#define HEADS 4
#define OUTD  256
#define NEG_SLOPE 0.2f

// GEMM tiling (wmma m16n16k16 bf16)
#define BM 128
#define BN 64
#define BK 64
#define LDS_AB 72                 // smem leading dim (elems), pad 8 vs 64
#define NN_PAD 50048              // 391 * 128 (grid-aligned padding)

// ---------------- scratch (static device globals) -------------------------------
__device__ __align__(16) float  g_h[(size_t)NN_PAD * OUTD];
__device__ __align__(16) __nv_bfloat16 g_xhi[(size_t)NN_PAD * IND];
__device__ __align__(16) __nv_bfloat16 g_xlo[(size_t)NN_PAD * IND];
__device__ __align__(16) __nv_bfloat16 g_whi[IND * OUTD];   // W [k][n], bf16 hi
__device__ __align__(16) __nv_bfloat16 g_wlo[IND * OUTD];   // W [k][n], bf16 lo
__device__ __align__(16) float4 g_asrc[NN];
__device__ __align__(16) float4 g_adst[NN];
__device__ __align__(16) int    g_count[NN];
__device__ __align__(16) int    g_off[NN + 1];
__device__ __align__(16) int    g_cursor[NN];
__device__ __align__(16) int    g_csrc[TOT_E];
__device__ int g_is64;

// ---------------- K0: probe edge_index dtype ------------------------------------
__global__ void probe_kernel(const int* __restrict__ ei32) {
    int any = 0;
    for (int i = threadIdx.x * 2 + 1; i < 8192; i += 2 * blockDim.x)
        any |= ei32[i];
    any = __syncthreads_or(any);
    if (threadIdx.x == 0) g_is64 = (any == 0) ? 1 : 0;
}
__device__ __forceinline__ int load_edge(const void* eiv, int idx) {
    int v = g_is64 ? (int)((const long long*)eiv)[idx] : ((const int*)eiv)[idx];
    return min(max(v, 0), NN - 1);
}

// ---------------- split-bf16 conversions ----------------------------------------
__global__ void convx_kernel(const float* __restrict__ x) {
    size_t i = (size_t)blockIdx.x * blockDim.x + threadIdx.x;   // one float4
    const size_t tot = (size_t)NN_PAD * IND / 4;
    if (i >= tot) return;
    float4 v = (i < (size_t)NN * IND / 4) ? ((const float4*)x)[i]
                                          : make_float4(0.f, 0.f, 0.f, 0.f);
    __nv_bfloat16 h0 = __float2bfloat16(v.x), h1 = __float2bfloat16(v.y);
    __nv_bfloat16 h2 = __float2bfloat16(v.z), h3 = __float2bfloat16(v.w);
    __nv_bfloat16 l0 = __float2bfloat16(v.x - __bfloat162float(h0));
    __nv_bfloat16 l1 = __float2bfloat16(v.y - __bfloat162float(h1));
    __nv_bfloat16 l2 = __float2bfloat16(v.z - __bfloat162float(h2));
    __nv_bfloat16 l3 = __float2bfloat16(v.w - __bfloat162float(h3));
    __nv_bfloat162* ph = (__nv_bfloat162*)g_xhi;
    __nv_bfloat162* pl = (__nv_bfloat162*)g_xlo;
    ph[i * 2]     = __nv_bfloat162(h0, h1);
    ph[i * 2 + 1] = __nv_bfloat162(h2, h3);
    pl[i * 2]     = __nv_bfloat162(l0, l1);
    pl[i * 2 + 1] = __nv_bfloat162(l2, l3);
}

__global__ void convw_kernel(const float* __restrict__ W) {
    int i = blockIdx.x * blockDim.x + threadIdx.x;   // k*256+n (layout preserved)
    if (i >= IND * OUTD) return;
    float v = W[i];
    __nv_bfloat16 h = __float2bfloat16(v);
    g_whi[i] = h;
    g_wlo[i] = __float2bfloat16(v - __bfloat162float(h));
}

// ---------------- K1: HMMA GEMM h = x @ W (split-bf16, cp.async 2-stage) --------
// per-stage smem layout: As_hi | As_lo | Bs_hi | Bs_lo
#define OFF_AHI 0
#define OFF_ALO (BM * LDS_AB * 2)                        // 18432
#define OFF_BHI (2 * BM * LDS_AB * 2)                    // 36864
#define OFF_BLO (2 * BM * LDS_AB * 2 + BK * LDS_AB * 2)  // 46080
#define STAGE_BYTES (2 * BM * LDS_AB * 2 + 2 * BK * LDS_AB * 2)  // 55296
#define SM_GEMM_TOTAL (2 * STAGE_BYTES)                  // 110592

__device__ __forceinline__ uint32_t smem_u32(const void* p) {
    uint32_t a;
    asm("{ .reg .u64 t; cvta.to.shared.u64 t, %1; cvt.u32.u64 %0, t; }"
        : "=r"(a) : "l"(p));
    return a;
}
__device__ __forceinline__ void cp16(uint32_t dst, const void* src) {
    asm volatile("cp.async.cg.shared.global [%0], [%1], 16;"
                 :: "r"(dst), "l"(src));
}
#define CP_COMMIT() asm volatile("cp.async.commit_group;" ::: "memory")
#define CP_WAIT1()  asm volatile("cp.async.wait_group 1;" ::: "memory")
#define CP_WAIT0()  asm volatile("cp.async.wait_group 0;" ::: "memory")

__global__ void __launch_bounds__(256, 1) gemm_wmma_kernel() {
    extern __shared__ char smem[];
    const uint32_t sb = smem_u32(smem);

    const int tid = threadIdx.x;
    const int wid = tid >> 5;
    const int warp_m = wid >> 1;          // 0..3
    const int warp_n = wid & 1;           // 0..1
    const int m0 = blockIdx.x * BM;
    const int n0 = blockIdx.y * BN;

    // per-thread load coordinates (same every tile)
    const int arow = tid >> 1;            // A: 128 rows, 2 threads/row
    const int ac8  = (tid & 1) * 32;      // 4 x 16B each, covering 64 cols
    const int brow = tid >> 2;            // B: 64 rows, 4 threads/row
    const int bc8  = (tid & 3) * 16;      // 2 x 16B each

    wmma::fragment<wmma::accumulator, 16, 16, 16, float> acc[2][2];
#pragma unroll
    for (int mi = 0; mi < 2; mi++)
#pragma unroll
        for (int ni = 0; ni < 2; ni++)
            wmma::fill_fragment(acc[mi][ni], 0.f);

    // async-load one K-tile into a stage
    auto load_tile = [&](int kt, int st) {
        const uint32_t s0 = sb + st * STAGE_BYTES;
        // A tile: 128 x 64 hi+lo (4 cp.async each per thread)
        const size_t ea = (size_t)(m0 + arow) * IND + kt + ac8;
        const uint32_t da = (uint32_t)((arow * LDS_AB + ac8) * 2);
#pragma unroll
        for (int q = 0; q < 4; q++) {
            cp16(s0 + OFF_AHI + da + q * 16, g_xhi + ea + q * 8);
            cp16(s0 + OFF_ALO + da + q * 16, g_xlo + ea + q * 8);
        }
        // B tile: 64 x 64 hi+lo (2 cp.async each per thread)
        const size_t eb = (size_t)(kt + brow) * OUTD + n0 + bc8;
        const uint32_t db = (uint32_t)((brow * LDS_AB + bc8) * 2);
#pragma unroll
        for (int q = 0; q < 2; q++) {
            cp16(s0 + OFF_BHI + db + q * 16, g_whi + eb + q * 8);
            cp16(s0 + OFF_BLO + db + q * 16, g_wlo + eb + q * 8);
        }
    };

    load_tile(0, 0);
    CP_COMMIT();

    const int NT = IND / BK;   // 4
    for (int t = 0; t < NT; t++) {
        if (t + 1 < NT) { load_tile((t + 1) * BK, (t + 1) & 1); CP_COMMIT(); }
        if (t + 1 < NT) CP_WAIT1(); else CP_WAIT0();
        __syncthreads();

        char* stg = smem + (t & 1) * STAGE_BYTES;
        __nv_bfloat16* As_hi = (__nv_bfloat16*)(stg + OFF_AHI);
        __nv_bfloat16* As_lo = (__nv_bfloat16*)(stg + OFF_ALO);
        __nv_bfloat16* Bs_hi = (__nv_bfloat16*)(stg + OFF_BHI);
        __nv_bfloat16* Bs_lo = (__nv_bfloat16*)(stg + OFF_BLO);

#pragma unroll
        for (int ks = 0; ks < BK; ks += 16) {
            wmma::fragment<wmma::matrix_a, 16, 16, 16, __nv_bfloat16, wmma::row_major> a_hi[2], a_lo[2];
            wmma::fragment<wmma::matrix_b, 16, 16, 16, __nv_bfloat16, wmma::row_major> b_hi[2], b_lo[2];
#pragma unroll
            for (int mi = 0; mi < 2; mi++) {
                const int r = warp_m * 32 + mi * 16;
                wmma::load_matrix_sync(a_hi[mi], As_hi + r * LDS_AB + ks, LDS_AB);
                wmma::load_matrix_sync(a_lo[mi], As_lo + r * LDS_AB + ks, LDS_AB);
            }
#pragma unroll
            for (int ni = 0; ni < 2; ni++) {
                const int c = warp_n * 32 + ni * 16;
                wmma::load_matrix_sync(b_hi[ni], Bs_hi + ks * LDS_AB + c, LDS_AB);
                wmma::load_matrix_sync(b_lo[ni], Bs_lo + ks * LDS_AB + c, LDS_AB);
            }
#pragma unroll
            for (int mi = 0; mi < 2; mi++)
#pragma unroll
                for (int ni = 0; ni < 2; ni++) {
                    wmma::mma_sync(acc[mi][ni], a_hi[mi], b_hi[ni], acc[mi][ni]);
                    wmma::mma_sync(acc[mi][ni], a_hi[mi], b_lo[ni], acc[mi][ni]);
                    wmma::mma_sync(acc[mi][ni], a_lo[mi], b_hi[ni], acc[mi][ni]);
                }
        }
        __syncthreads();   // stage (t&1) free for reuse at t+2's prefetch
    }

    // epilogue: unguarded stores into padded g_h
#pragma unroll
    for (int mi = 0; mi < 2; mi++)
#pragma unroll
        for (int ni = 0; ni < 2; ni++) {
            const int r = m0 + warp_m * 32 + mi * 16;
            const int c = n0 + warp_n * 32 + ni * 16;
            wmma::store_matrix_sync(g_h + (size_t)r * OUTD + c, acc[mi][ni],
                                    OUTD, wmma::mem_row_major);
        }
}

// ---------------- K2: per-node attention logits ---------------------------------
__global__ void att_kernel(const float* __restrict__ att_s,
                           const float* __restrict__ att_d) {
    const int gw   = (blockIdx.x * blockDim.x + threadIdx.x) >> 5;
    const int lane = threadIdx.x & 31;
    if (gw >= NN) return;

    const float* hrow = g_h + (size_t)gw * OUTD;
    float4 h0 = *(const float4*)(hrow + lane * 8);
    float4 h1 = *(const float4*)(hrow + lane * 8 + 4);
    float4 s0 = *(const float4*)(att_s + lane * 8);
    float4 s1 = *(const float4*)(att_s + lane * 8 + 4);
    float4 d0 = *(const float4*)(att_d + lane * 8);
    float4 d1 = *(const float4*)(att_d + lane * 8 + 4);

    float ps = h0.x * s0.x + h0.y * s0.y + h0.z * s0.z + h0.w * s0.w
             + h1.x * s1.x + h1.y * s1.y + h1.z * s1.z + h1.w * s1.w;
    float pd = h0.x * d0.x + h0.y * d0.y + h0.z * d0.z + h0.w * d0.w
             + h1.x * d1.x + h1.y * d1.y + h1.z * d1.z + h1.w * d1.w;

#pragma unroll
    for (int o = 1; o < 8; o <<= 1) {
        ps += __shfl_xor_sync(0xffffffffu, ps, o);
        pd += __shfl_xor_sync(0xffffffffu, pd, o);
    }
    if ((lane & 7) == 0) {
        const int head = lane >> 3;
        ((float*)g_asrc)[(size_t)gw * 4 + head] = ps;
        ((float*)g_adst)[(size_t)gw * 4 + head] = pd;
    }
}

// ---------------- CSR build by destination --------------------------------------
__global__ void zero_kernel() {
    int i = blockIdx.x * blockDim.x + threadIdx.x;
    if (i < NN) g_count[i] = 0;
}
__global__ void count_kernel(const void* __restrict__ eiv) {
    int e = blockIdx.x * blockDim.x + threadIdx.x;
    if (e >= TOT_E) return;
    int d = (e < EE) ? load_edge(eiv, EE + e) : (e - EE);
    atomicAdd(&g_count[d], 1);
}
__global__ void scan_kernel() {
    __shared__ int s[1024];
    const int tid = threadIdx.x;
    const int CH = (NN + 1023) / 1024;
    const int base = tid * CH;
    int mysum = 0;
    for (int i = 0; i < CH; i++) {
        int idx = base + i;
        if (idx < NN) mysum += g_count[idx];
    }
    s[tid] = mysum;
    __syncthreads();
#pragma unroll
    for (int o = 1; o < 1024; o <<= 1) {
        int t = (tid >= o) ? s[tid - o] : 0;
        __syncthreads();
        s[tid] += t;
        __syncthreads();
    }
    int excl = s[tid] - mysum;
    for (int i = 0; i < CH; i++) {
        int idx = base + i;
        if (idx < NN) {
            g_off[idx]    = excl;
            g_cursor[idx] = excl;
            excl += g_count[idx];
        }
    }
    if (tid == 1023) g_off[NN] = excl;
}
__global__ void scatter_kernel(const void* __restrict__ eiv) {
    int e = blockIdx.x * blockDim.x + threadIdx.x;
    if (e >= TOT_E) return;
    int sN, d;
    if (e < EE) { sN = load_edge(eiv, e); d = load_edge(eiv, EE + e); }
    else        { sN = d = e - EE; }
    int pos = atomicAdd(&g_cursor[d], 1);
    if (pos >= 0 && pos < TOT_E) g_csrc[pos] = sN;
}

// ---------------- K6: segment softmax + weighted aggregation --------------------
__device__ __forceinline__ float leaky(float v) {
    return v > 0.f ? v : NEG_SLOPE * v;
}

__global__ void aggregate_kernel(const float* __restrict__ bias,
                                 float* __restrict__ out) {
    const int gw   = (blockIdx.x * blockDim.x + threadIdx.x) >> 5;
    const int lane = threadIdx.x & 31;
    if (gw >= NN) return;

    const int beg = g_off[gw];
    const int end = g_off[gw + 1];
    const float4 ad = g_adst[gw];

    float m0 = -1e30f, m1 = -1e30f, m2 = -1e30f, m3 = -1e30f;
    for (int i = beg + lane; i < end; i += 32) {
        int sN = g_csrc[i];
        float4 as = g_asrc[sN];
        m0 = fmaxf(m0, leaky(as.x + ad.x));
        m1 = fmaxf(m1, leaky(as.y + ad.y));
        m2 = fmaxf(m2, leaky(as.z + ad.z));
        m3 = fmaxf(m3, leaky(as.w + ad.w));
    }
#pragma unroll
    for (int o = 16; o > 0; o >>= 1) {
        m0 = fmaxf(m0, __shfl_xor_sync(0xffffffffu, m0, o));
        m1 = fmaxf(m1, __shfl_xor_sync(0xffffffffu, m1, o));
        m2 = fmaxf(m2, __shfl_xor_sync(0xffffffffu, m2, o));
        m3 = fmaxf(m3, __shfl_xor_sync(0xffffffffu, m3, o));
    }

    float d0 = 0.f, d1 = 0.f, d2 = 0.f, d3 = 0.f;
    for (int i = beg + lane; i < end; i += 32) {
        int sN = g_csrc[i];
        float4 as = g_asrc[sN];
        d0 += __expf(leaky(as.x + ad.x) - m0);
        d1 += __expf(leaky(as.y + ad.y) - m1);
        d2 += __expf(leaky(as.z + ad.z) - m2);
        d3 += __expf(leaky(as.w + ad.w) - m3);
    }
#pragma unroll
    for (int o = 16; o > 0; o >>= 1) {
        d0 += __shfl_xor_sync(0xffffffffu, d0, o);
        d1 += __shfl_xor_sync(0xffffffffu, d1, o);
        d2 += __shfl_xor_sync(0xffffffffu, d2, o);
        d3 += __shfl_xor_sync(0xffffffffu, d3, o);
    }
    const float i0 = 1.f / d0, i1 = 1.f / d1, i2 = 1.f / d2, i3 = 1.f / d3;

    float4 acc0 = make_float4(0.f, 0.f, 0.f, 0.f);
    float4 acc1 = make_float4(0.f, 0.f, 0.f, 0.f);
    const bool lo = (lane < 16);

    const int nume = end - beg;
    for (int base = 0; base < nume; base += 32) {
        const int cnt = min(32, nume - base);
        const bool valid = (base + lane < nume);
        int   sv = valid ? g_csrc[beg + base + lane] : 0;
        float a0 = 0.f, a1 = 0.f, a2 = 0.f, a3 = 0.f;
        if (valid) {
            float4 as = g_asrc[sv];
            a0 = __expf(leaky(as.x + ad.x) - m0) * i0;
            a1 = __expf(leaky(as.y + ad.y) - m1) * i1;
            a2 = __expf(leaky(as.z + ad.z) - m2) * i2;
            a3 = __expf(leaky(as.w + ad.w) - m3) * i3;
        }
        for (int j = 0; j < cnt; j++) {
            const int   sN = __shfl_sync(0xffffffffu, sv, j);
            const float s0 = __shfl_sync(0xffffffffu, a0, j);
            const float s1 = __shfl_sync(0xffffffffu, a1, j);
            const float s2 = __shfl_sync(0xffffffffu, a2, j);
            const float s3 = __shfl_sync(0xffffffffu, a3, j);
            const float w0 = lo ? s0 : s1;
            const float w1 = lo ? s2 : s3;
            const float4* hp = (const float4*)(g_h + (size_t)sN * OUTD);
            float4 v0 = hp[lane];
            float4 v1 = hp[32 + lane];
            acc0.x += w0 * v0.x; acc0.y += w0 * v0.y;
            acc0.z += w0 * v0.z; acc0.w += w0 * v0.w;
            acc1.x += w1 * v1.x; acc1.y += w1 * v1.y;
            acc1.z += w1 * v1.z; acc1.w += w1 * v1.w;
        }
    }

    float4 b0 = *(const float4*)(bias + lane * 4);
    float4 b1 = *(const float4*)(bias + 128 + lane * 4);
    acc0.x = fmaxf(acc0.x + b0.x, 0.f); acc0.y = fmaxf(acc0.y + b0.y, 0.f);
    acc0.z = fmaxf(acc0.z + b0.z, 0.f); acc0.w = fmaxf(acc0.w + b0.w, 0.f);
    acc1.x = fmaxf(acc1.x + b1.x, 0.f); acc1.y = fmaxf(acc1.y + b1.y, 0.f);
    acc1.w = fmaxf(acc1.w + b1.w, 0.f); acc1.z = fmaxf(acc1.z + b1.z, 0.f);

    float4* op = (float4*)(out + (size_t)gw * OUTD);
    op[lane]      = acc0;
    op[32 + lane] = acc1;
}

// ---------------- launch --------------------------------------------------------
extern "C" void kernel_launch(void* const* d_in, const int* in_sizes, int n_in,
                              void* d_out, int out_size) {
    const float* x = nullptr; const void* ei = nullptr; const float* W = nullptr;
    const float* att_src = nullptr; const float* att_dst = nullptr;
    const float* bias = nullptr;
    for (int i = 0; i < n_in; i++) {
        const int sz = in_sizes[i];
        if (sz == 12800000)      { x = (const float*)d_in[i]; }
        else if (sz == 65536)    { W = (const float*)d_in[i]; }
        else if (sz >= 1000000)  { ei = d_in[i]; }
        else if (sz == 256) {
            if      (!att_src) att_src = (const float*)d_in[i];
            else if (!att_dst) att_dst = (const float*)d_in[i];
            else if (!bias)    bias    = (const float*)d_in[i];
        }
    }
    float* out = (float*)d_out;
    (void)out_size;
    if (!x || !ei || !W || !att_src || !att_dst || !bias) return;

    // one-time setup (runs on the uncaptured correctness call; no device allocs)
    static cudaStream_t s_side = nullptr;
    static cudaEvent_t  ev_fork = nullptr, ev_join = nullptr;
    static bool init_done = false;
    if (!init_done) {
        cudaFuncSetAttribute(gemm_wmma_kernel,
                             cudaFuncAttributeMaxDynamicSharedMemorySize,
                             SM_GEMM_TOTAL);
        cudaStreamCreateWithFlags(&s_side, cudaStreamNonBlocking);
        cudaEventCreateWithFlags(&ev_fork, cudaEventDisableTiming);
        cudaEventCreateWithFlags(&ev_join, cudaEventDisableTiming);
        init_done = true;
    }

    // main stream: probe, then fork CSR chain to side stream
    probe_kernel<<<1, 256>>>((const int*)ei);
    cudaEventRecord(ev_fork, 0);
    cudaStreamWaitEvent(s_side, ev_fork, 0);

    // side stream: CSR build (independent of GEMM path)
    zero_kernel<<<(NN + 255) / 256, 256, 0, s_side>>>();
    count_kernel<<<(TOT_E + 255) / 256, 256, 0, s_side>>>(ei);
    scan_kernel<<<1, 1024, 0, s_side>>>();
    scatter_kernel<<<(TOT_E + 255) / 256, 256, 0, s_side>>>(ei);
    cudaEventRecord(ev_join, s_side);

    // main stream: conversion + GEMM + att logits
    convw_kernel<<<(IND * OUTD + 255) / 256, 256>>>(W);
    convx_kernel<<<(int)(((size_t)NN_PAD * IND / 4 + 255) / 256), 256>>>(x);
    gemm_wmma_kernel<<<dim3(NN_PAD / BM, OUTD / BN), 256, SM_GEMM_TOTAL>>>();
    att_kernel<<<(NN + 7) / 8, 256>>>(att_src, att_dst);

    // join and aggregate
    cudaStreamWaitEvent(0, ev_join, 0);
    aggregate_kernel<<<(NN + 7) / 8, 256>>>(bias, out);
}